// round 16
// baseline (speedup 1.0000x reference)
#include <cuda_runtime.h>
#include <cuda_fp16.h>
#include <cstdint>

#define T_DIM 2048
#define B_DIM 2
#define E_DIM 1024
#define H_DIM 16
#define D_H   64
#define M_DIM 4096

// fp16 scratch
__device__ __half g_q[(size_t)M_DIM * E_DIM];
__device__ __half g_k[(size_t)M_DIM * E_DIM];
__device__ __half g_v[(size_t)M_DIM * E_DIM];
__device__ __half g_ctx[(size_t)M_DIM * E_DIM];
__device__ __half g_xq[(size_t)M_DIM * E_DIM];
__device__ __half g_xk[(size_t)M_DIM * E_DIM];
__device__ __half g_xv[(size_t)M_DIM * E_DIM];
__device__ __half g_wi[(size_t)3 * E_DIM * E_DIM];
__device__ __half g_wo[(size_t)E_DIM * E_DIM];

// ---------------------------------------------------------------------------
__device__ __forceinline__ unsigned sptr(const void* p) {
    return (unsigned)__cvta_generic_to_shared(p);
}
__device__ __forceinline__ void mma_f16(float* c,
    unsigned a0, unsigned a1, unsigned a2, unsigned a3,
    unsigned b0, unsigned b1)
{
    asm volatile(
        "mma.sync.aligned.m16n8k16.row.col.f32.f16.f16.f32 "
        "{%0,%1,%2,%3},{%4,%5,%6,%7},{%8,%9},{%0,%1,%2,%3};"
        : "+f"(c[0]), "+f"(c[1]), "+f"(c[2]), "+f"(c[3])
        : "r"(a0), "r"(a1), "r"(a2), "r"(a3), "r"(b0), "r"(b1));
}
__device__ __forceinline__ void mma_f16h(unsigned* c,
    unsigned a0, unsigned a1, unsigned a2, unsigned a3,
    unsigned b0, unsigned b1)
{
    asm volatile(
        "mma.sync.aligned.m16n8k16.row.col.f16.f16.f16.f16 "
        "{%0,%1},{%2,%3,%4,%5},{%6,%7},{%0,%1};"
        : "+r"(c[0]), "+r"(c[1])
        : "r"(a0), "r"(a1), "r"(a2), "r"(a3), "r"(b0), "r"(b1));
}
__device__ __forceinline__ void ldmx4(unsigned* r, unsigned addr) {
    asm volatile("ldmatrix.sync.aligned.m8n8.x4.shared.b16 {%0,%1,%2,%3},[%4];"
        : "=r"(r[0]), "=r"(r[1]), "=r"(r[2]), "=r"(r[3]) : "r"(addr));
}
__device__ __forceinline__ void ldmx4t(unsigned* r, unsigned addr) {
    asm volatile("ldmatrix.sync.aligned.m8n8.x4.trans.shared.b16 {%0,%1,%2,%3},[%4];"
        : "=r"(r[0]), "=r"(r[1]), "=r"(r[2]), "=r"(r[3]) : "r"(addr));
}
__device__ __forceinline__ void cpa16(void* dst, const void* src) {
    unsigned d = sptr(dst);
    asm volatile("cp.async.cg.shared.global [%0], [%1], 16;" :: "r"(d), "l"(src));
}
__device__ __forceinline__ void cp_commit() {
    asm volatile("cp.async.commit_group;");
}
template <int N>
__device__ __forceinline__ void cp_wait() {
    asm volatile("cp.async.wait_group %0;" :: "n"(N));
}
__device__ __forceinline__ unsigned h2(float a, float b) {
    __half2 h = __floats2half2_rn(a, b);
    return *reinterpret_cast<unsigned*>(&h);
}
__device__ __forceinline__ unsigned ex2h(unsigned x) {
    __half2 u = *reinterpret_cast<__half2*>(&x);
    const unsigned c15u = 0x4B804B80u;
    u = __hmin2(u, *reinterpret_cast<const __half2*>(&c15u));
    unsigned xx = *reinterpret_cast<unsigned*>(&u);
    unsigned y;
    asm("ex2.approx.f16x2 %0, %1;" : "=r"(y) : "r"(xx));
    return y;
}

// ---------------------------------------------------------------------------
// Batched pre-pass: round 5 fp32 arrays -> fp16 in ONE launch, MLP=4.
// ---------------------------------------------------------------------------
__global__ void round_all(
    const float4* s0, uint2* d0, int n0,
    const float4* s1, uint2* d1, int n1,
    const float4* s2, uint2* d2, int n2,
    const float4* s3, uint2* d3, int n3,
    const float4* s4, uint2* d4, int n4)
{
    const float4* s;
    uint2* d;
    int n;
    switch (blockIdx.y) {
        case 0: s = s0; d = d0; n = n0; break;
        case 1: s = s1; d = d1; n = n1; break;
        case 2: s = s2; d = d2; n = n2; break;
        case 3: s = s3; d = d3; n = n3; break;
        default: s = s4; d = d4; n = n4; break;
    }
    int base = blockIdx.x * (256 * 4) + threadIdx.x;
    float4 v[4];
    int idx[4];
    int cnt = 0;
#pragma unroll
    for (int u = 0; u < 4; u++) {
        int i = base + u * 256;
        if (i < n) { idx[cnt] = i; v[cnt] = s[i]; cnt++; }
    }
#pragma unroll
    for (int u = 0; u < 4; u++) {
        if (u < cnt) {
            uint2 o;
            o.x = h2(v[u].x, v[u].y);
            o.y = h2(v[u].z, v[u].w);
            d[idx[u]] = o;
        }
    }
}

// ---------------------------------------------------------------------------
// fp16 GEMM, barrier-amortized: block tile 64x128, 128 threads (4 warps,
// warp tile 32x64), BK=64 -> 64 mmas per warp per barrier (2x R14), 6 ldsm
// per 16 mmas. 3-stage cp.async ring, 2 CTAs/SM.
// LAYOUT 0: scatter half2 into (B,H,T,Dh); chunk of bn selects X/dst;
//           q chunk pre-scaled by 0.125*log2(e). LAYOUT 1: fp32 (M,E) store.
// ---------------------------------------------------------------------------
#define PJ_STRIDE 72
#define PJX_BYTES (64 * PJ_STRIDE * 2)      // 9216
#define PJW_BYTES (128 * PJ_STRIDE * 2)     // 18432
#define PJ_STG    (PJX_BYTES + PJW_BYTES)   // 27648
#define PJ_SMEM   (3 * PJ_STG)              // 82944 -> 2 CTAs/SM
#define PJ_NIT    (E_DIM / 64)              // 16

template <int LAYOUT>
__global__ __launch_bounds__(128, 2) void proj_mma(
    const __half* __restrict__ Xq, const __half* __restrict__ Xk,
    const __half* __restrict__ Xv,
    const __half* __restrict__ W, const float* __restrict__ bias,
    void* __restrict__ outq, void* __restrict__ outk, void* __restrict__ outv)
{
    extern __shared__ char psm[];

    const int tid  = threadIdx.x;
    const int lane = tid & 31;
    const int w    = tid >> 5;        // 0..3
    const int g    = lane >> 2;
    const int t    = lane & 3;
    const int quad = lane >> 3;
    const int lq   = lane & 7;
    const int wm   = w >> 1;          // 0..1 (32 rows each)
    const int wn   = w & 1;           // 0..1 (64 cols each)
    const int bm   = blockIdx.x * 64;
    const int bn   = blockIdx.y * 128;
    const int chunk = (LAYOUT == 0) ? (bn >> 10) : 0;

    const __half* X = (chunk == 0) ? Xq : (chunk == 1 ? Xk : Xv);

    float acc[2][8][4];               // 2 m-frags x 8 n-frags
#pragma unroll
    for (int i = 0; i < 2; i++)
#pragma unroll
        for (int j = 0; j < 8; j++)
#pragma unroll
            for (int r = 0; r < 4; r++) acc[i][j][r] = 0.0f;

    const int cr = tid >> 3;          // 0..15
    const int cq = tid & 7;           // chunk-of-8-halves within BK=64

    auto stage_load = [&](int st, int k0) {
        __half* Xs = reinterpret_cast<__half*>(psm + st * PJ_STG);
        __half* Ws = reinterpret_cast<__half*>(psm + st * PJ_STG + PJX_BYTES);
#pragma unroll
        for (int i = 0; i < 4; i++) {
            int r = cr + i * 16;
            cpa16(&Xs[r * PJ_STRIDE + cq * 8], X + (size_t)(bm + r) * E_DIM + k0 + cq * 8);
        }
#pragma unroll
        for (int i = 0; i < 8; i++) {
            int r = cr + i * 16;
            cpa16(&Ws[r * PJ_STRIDE + cq * 8], W + (size_t)(bn + r) * E_DIM + k0 + cq * 8);
        }
        cp_commit();
    };

    stage_load(0, 0);
    stage_load(1, 64);

    const unsigned base0 = sptr(psm);
    const int a_row  = wm * 32 + (quad & 1) * 8 + lq;
    const int a_colB = ((quad >> 1) * 8) * 2;
    const int b_row  = wn * 64 + (quad >> 1) * 8 + lq;
    const int b_colB = ((quad & 1) * 8) * 2;

    for (int it = 0; it < PJ_NIT; ++it) {
        cp_wait<1>();
        __syncthreads();
        if (it + 2 < PJ_NIT) {
            stage_load((it + 2) % 3, (it + 2) * 64);
        } else {
            cp_commit();
        }

        const int st = it % 3;
        const unsigned xb = base0 + st * PJ_STG;
        const unsigned wb = xb + PJX_BYTES;
#pragma unroll
        for (int ks = 0; ks < 4; ++ks) {
            const int k0B = ks * 32;
            unsigned kb[4][4];
            unsigned a[2][4];
#pragma unroll
            for (int ng = 0; ng < 4; ++ng)
                ldmx4(kb[ng], wb + (unsigned)(b_row + ng * 16) * (PJ_STRIDE * 2) + k0B + b_colB);
#pragma unroll
            for (int mt = 0; mt < 2; ++mt)
                ldmx4(a[mt], xb + (unsigned)(a_row + mt * 16) * (PJ_STRIDE * 2) + k0B + a_colB);
#pragma unroll
            for (int mt = 0; mt < 2; ++mt)
#pragma unroll
                for (int ng = 0; ng < 4; ++ng) {
                    mma_f16(acc[mt][2 * ng],     a[mt][0], a[mt][1], a[mt][2], a[mt][3],
                            kb[ng][0], kb[ng][1]);
                    mma_f16(acc[mt][2 * ng + 1], a[mt][0], a[mt][1], a[mt][2], a[mt][3],
                            kb[ng][2], kb[ng][3]);
                }
        }
    }

    const float sc = (LAYOUT == 0 && chunk == 0) ? 0.1803368801111204f : 1.0f;
#pragma unroll
    for (int mt = 0; mt < 2; ++mt) {
        int r0 = bm + wm * 32 + mt * 16 + g;
#pragma unroll
        for (int nt = 0; nt < 8; ++nt) {
            int n = bn + wn * 64 + nt * 8 + 2 * t;
            float bv0 = bias[n];
            float bv1 = bias[n + 1];
            float v0 = acc[mt][nt][0] + bv0;
            float v1 = acc[mt][nt][1] + bv1;
            float v2 = acc[mt][nt][2] + bv0;
            float v3 = acc[mt][nt][3] + bv1;
            if (LAYOUT == 0) {
                int nn = n & 1023;
                int hh = nn >> 6;
                int dd = nn & 63;
                __half* dst = (__half*)((chunk == 0) ? outq : (chunk == 1 ? outk : outv));
                {
                    int r = r0;
                    size_t a0 = ((size_t)((r & 1) * H_DIM + hh) * T_DIM + (r >> 1)) * D_H + dd;
                    *reinterpret_cast<unsigned*>(&dst[a0]) = h2(v0 * sc, v1 * sc);
                }
                {
                    int r = r0 + 8;
                    size_t a1 = ((size_t)((r & 1) * H_DIM + hh) * T_DIM + (r >> 1)) * D_H + dd;
                    *reinterpret_cast<unsigned*>(&dst[a1]) = h2(v2 * sc, v3 * sc);
                }
            } else {
                float* dst = (float*)outq;
                *reinterpret_cast<float2*>(&dst[(size_t)r0 * E_DIM + n]) = make_float2(v0, v1);
                *reinterpret_cast<float2*>(&dst[(size_t)(r0 + 8) * E_DIM + n]) = make_float2(v2, v3);
            }
        }
    }
}

// ---------------------------------------------------------------------------
// fp16 flash attention (R13/R14 best, unchanged): 128-thread CTAs, Q tile 128
// (32 rows/warp), KV 64, 3-slot ring, 3 CTAs/SM, f16-accum S -> PV A-frag.
// ---------------------------------------------------------------------------
#define QS_STRIDE 72
#define AQ_ROWS   128
#define KV_HALVES (64 * QS_STRIDE)
#define ATTN_SMEM_HALVES (AQ_ROWS * QS_STRIDE + 3 * 2 * KV_HALVES)
#define ATTN_SMEM_BYTES  (ATTN_SMEM_HALVES * 2)
#define N_KV (T_DIM / 64)

__global__ __launch_bounds__(128, 3) void attn_mma(
    const __half* __restrict__ Q, const __half* __restrict__ K,
    const __half* __restrict__ V, __half* __restrict__ ctx)
{
    extern __shared__ __half smh[];
    __half* Qs  = smh;
    __half* KVs = smh + AQ_ROWS * QS_STRIDE;

    const int tid  = threadIdx.x;
    const int lane = tid & 31;
    const int w    = tid >> 5;
    const int g    = lane >> 2;
    const int t    = lane & 3;
    const int quad = lane >> 3;
    const int lq   = lane & 7;
    const int qt   = blockIdx.x;
    const int bh   = blockIdx.y;
    const int b    = bh >> 4;
    const int h    = bh & 15;
    const int m0   = w * 32;

    const __half* Qh = Q + (size_t)bh * T_DIM * D_H + (size_t)qt * AQ_ROWS * D_H;
    const __half* Kh = K + (size_t)bh * T_DIM * D_H;
    const __half* Vh = V + (size_t)bh * T_DIM * D_H;

    const int lr = tid >> 3;
    const int lc = tid & 7;

    auto kv_load = [&](int kv) {
        const int slot = kv % 3;
        __half* Kd = KVs + slot * 2 * KV_HALVES;
        __half* Vd = Kd + KV_HALVES;
        const __half* Kn = Kh + (size_t)kv * 64 * D_H;
        const __half* Vn = Vh + (size_t)kv * 64 * D_H;
#pragma unroll
        for (int i = 0; i < 4; i++) {
            int r = lr + i * 16;
            cpa16(&Kd[r * QS_STRIDE + lc * 8], Kn + (size_t)r * D_H + lc * 8);
            cpa16(&Vd[r * QS_STRIDE + lc * 8], Vn + (size_t)r * D_H + lc * 8);
        }
        cp_commit();
    };

#pragma unroll
    for (int i = 0; i < 8; i++) {
        int r = lr + i * 16;
        cpa16(&Qs[r * QS_STRIDE + lc * 8], Qh + (size_t)r * D_H + lc * 8);
    }
    cp_commit();
    kv_load(0);
    kv_load(1);

    cp_wait<2>();
    __syncthreads();

    const unsigned qbase  = sptr(Qs);
    const unsigned kvbase = sptr(KVs);
    unsigned qf[4][2][4];
    {
        int colB = ((quad >> 1) * 8) * 2;
#pragma unroll
        for (int mt = 0; mt < 2; ++mt) {
            int row = m0 + mt * 16 + (quad & 1) * 8 + lq;
#pragma unroll
            for (int kt = 0; kt < 4; ++kt)
                ldmx4(qf[kt][mt], qbase + (unsigned)row * (QS_STRIDE * 2) + kt * 32 + colB);
        }
    }

    float o[2][8][4];
#pragma unroll
    for (int mt = 0; mt < 2; mt++)
#pragma unroll
        for (int nt = 0; nt < 8; nt++)
#pragma unroll
            for (int r = 0; r < 4; r++) o[mt][nt][r] = 0.0f;
    float lacc[2][4];
#pragma unroll
    for (int mt = 0; mt < 2; mt++)
#pragma unroll
        for (int r = 0; r < 4; r++) lacc[mt][r] = 0.0f;
    const unsigned ONES = 0x3C003C00u;

    const int k_row  = (quad >> 1) * 8 + lq;
    const int k_colB = ((quad & 1) * 8) * 2;
    const int v_row  = (quad & 1) * 8 + lq;
    const int v_colB = ((quad >> 1) * 8) * 2;

    for (int kv = 0; kv < N_KV; ++kv) {
        if (kv < N_KV - 2) {
            cp_wait<1>();
        } else {
            cp_wait<0>();
        }
        __syncthreads();
        if (kv + 2 < N_KV)
            kv_load(kv + 2);

        const unsigned kb_ = kvbase + (unsigned)(kv % 3) * (2 * KV_HALVES * 2);
        const unsigned vb_ = kb_ + KV_HALVES * 2;

#pragma unroll
        for (int ng = 0; ng < 4; ++ng) {
            unsigned kb[4][4];
#pragma unroll
            for (int kt = 0; kt < 4; ++kt)
                ldmx4(kb[kt], kb_ + (unsigned)(ng * 16 + k_row) * (QS_STRIDE * 2) + kt * 32 + k_colB);

            unsigned pp[2][4];
#pragma unroll
            for (int mt = 0; mt < 2; ++mt) {
                unsigned s0[2] = {0u, 0u};
                unsigned s1[2] = {0u, 0u};
#pragma unroll
                for (int kt = 0; kt < 4; ++kt) {
                    mma_f16h(s0, qf[kt][mt][0], qf[kt][mt][1], qf[kt][mt][2], qf[kt][mt][3],
                             kb[kt][0], kb[kt][1]);
                    mma_f16h(s1, qf[kt][mt][0], qf[kt][mt][1], qf[kt][mt][2], qf[kt][mt][3],
                             kb[kt][2], kb[kt][3]);
                }
                pp[mt][0] = ex2h(s0[0]);
                pp[mt][1] = ex2h(s0[1]);
                pp[mt][2] = ex2h(s1[0]);
                pp[mt][3] = ex2h(s1[1]);
                mma_f16(lacc[mt], pp[mt][0], pp[mt][1], pp[mt][2], pp[mt][3], ONES, ONES);
            }

#pragma unroll
            for (int dg = 0; dg < 4; ++dg) {
                unsigned vb[4];
                ldmx4t(vb, vb_ + (unsigned)(ng * 16 + v_row) * (QS_STRIDE * 2) + dg * 32 + v_colB);
#pragma unroll
                for (int mt = 0; mt < 2; ++mt) {
                    mma_f16(o[mt][2 * dg],     pp[mt][0], pp[mt][1], pp[mt][2], pp[mt][3],
                            vb[0], vb[1]);
                    mma_f16(o[mt][2 * dg + 1], pp[mt][0], pp[mt][1], pp[mt][2], pp[mt][3],
                            vb[2], vb[3]);
                }
            }
        }
    }

#pragma unroll
    for (int mt = 0; mt < 2; ++mt) {
        float inv0 = 1.0f / lacc[mt][0];
        float inv1 = 1.0f / lacc[mt][2];
        int r0 = qt * AQ_ROWS + m0 + mt * 16 + g;
#pragma unroll
        for (int nt = 0; nt < 8; ++nt) {
            int d = nt * 8 + 2 * t;
            size_t a0 = ((size_t)r0 * B_DIM + b) * E_DIM + h * 64 + d;
            size_t a1 = ((size_t)(r0 + 8) * B_DIM + b) * E_DIM + h * 64 + d;
            *reinterpret_cast<unsigned*>(&ctx[a0]) = h2(o[mt][nt][0] * inv0, o[mt][nt][1] * inv0);
            *reinterpret_cast<unsigned*>(&ctx[a1]) = h2(o[mt][nt][2] * inv1, o[mt][nt][3] * inv1);
        }
    }
}

// ---------------------------------------------------------------------------
extern "C" void kernel_launch(void* const* d_in, const int* in_sizes, int n_in,
                              void* d_out, int out_size)
{
    const float* query = (const float*)d_in[0];
    const float* key   = (const float*)d_in[1];
    const float* value = (const float*)d_in[2];
    const float* in_w  = (const float*)d_in[3];
    const float* in_b  = (const float*)d_in[4];
    const float* out_w = (const float*)d_in[5];
    const float* out_b = (const float*)d_in[6];
    float* out = (float*)d_out;

    __half *qp, *kp, *vp, *cp, *xq, *xk, *xv, *wi, *wo;
    cudaGetSymbolAddress((void**)&qp, g_q);
    cudaGetSymbolAddress((void**)&kp, g_k);
    cudaGetSymbolAddress((void**)&vp, g_v);
    cudaGetSymbolAddress((void**)&cp, g_ctx);
    cudaGetSymbolAddress((void**)&xq, g_xq);
    cudaGetSymbolAddress((void**)&xk, g_xk);
    cudaGetSymbolAddress((void**)&xv, g_xv);
    cudaGetSymbolAddress((void**)&wi, g_wi);
    cudaGetSymbolAddress((void**)&wo, g_wo);

    cudaFuncSetAttribute(attn_mma, cudaFuncAttributeMaxDynamicSharedMemorySize,
                         ATTN_SMEM_BYTES);
    cudaFuncSetAttribute(proj_mma<0>, cudaFuncAttributeMaxDynamicSharedMemorySize,
                         PJ_SMEM);
    cudaFuncSetAttribute(proj_mma<1>, cudaFuncAttributeMaxDynamicSharedMemorySize,
                         PJ_SMEM);

    const int N_IN = M_DIM * E_DIM / 4;
    const int N_WI = 3 * E_DIM * E_DIM / 4;
    const int N_WO = E_DIM * E_DIM / 4;
    round_all<<<dim3((N_IN + 1023) / 1024, 5), 256>>>(
        (const float4*)query, (uint2*)xq, N_IN,
        (const float4*)key,   (uint2*)xk, N_IN,
        (const float4*)value, (uint2*)xv, N_IN,
        (const float4*)in_w,  (uint2*)wi, N_WI,
        (const float4*)out_w, (uint2*)wo, N_WO);

    proj_mma<0><<<dim3(M_DIM / 64, 24), 128, PJ_SMEM>>>(
        xq, xk, xv, wi, in_b, qp, kp, vp);

    attn_mma<<<dim3(T_DIM / AQ_ROWS, B_DIM * H_DIM), 128, ATTN_SMEM_BYTES>>>(qp, kp, vp, cp);

    proj_mma<1><<<dim3(M_DIM / 64, 8), 128, PJ_SMEM>>>(
        cp, cp, cp, wo, out_b, out, out, out);
}

// round 17
// speedup vs baseline: 1.0273x; 1.0273x over previous
#include <cuda_runtime.h>
#include <cuda_fp16.h>
#include <cstdint>

#define T_DIM 2048
#define B_DIM 2
#define E_DIM 1024
#define H_DIM 16
#define D_H   64
#define M_DIM 4096

// fp16 scratch
__device__ __half g_q[(size_t)M_DIM * E_DIM];
__device__ __half g_k[(size_t)M_DIM * E_DIM];
__device__ __half g_v[(size_t)M_DIM * E_DIM];
__device__ __half g_ctx[(size_t)M_DIM * E_DIM];
__device__ __half g_xq[(size_t)M_DIM * E_DIM];
__device__ __half g_xk[(size_t)M_DIM * E_DIM];
__device__ __half g_xv[(size_t)M_DIM * E_DIM];
__device__ __half g_wi[(size_t)3 * E_DIM * E_DIM];
__device__ __half g_wo[(size_t)E_DIM * E_DIM];

// ---------------------------------------------------------------------------
__device__ __forceinline__ unsigned sptr(const void* p) {
    return (unsigned)__cvta_generic_to_shared(p);
}
__device__ __forceinline__ void mma_f16(float* c,
    unsigned a0, unsigned a1, unsigned a2, unsigned a3,
    unsigned b0, unsigned b1)
{
    asm volatile(
        "mma.sync.aligned.m16n8k16.row.col.f32.f16.f16.f32 "
        "{%0,%1,%2,%3},{%4,%5,%6,%7},{%8,%9},{%0,%1,%2,%3};"
        : "+f"(c[0]), "+f"(c[1]), "+f"(c[2]), "+f"(c[3])
        : "r"(a0), "r"(a1), "r"(a2), "r"(a3), "r"(b0), "r"(b1));
}
__device__ __forceinline__ void mma_f16h(unsigned* c,
    unsigned a0, unsigned a1, unsigned a2, unsigned a3,
    unsigned b0, unsigned b1)
{
    asm volatile(
        "mma.sync.aligned.m16n8k16.row.col.f16.f16.f16.f16 "
        "{%0,%1},{%2,%3,%4,%5},{%6,%7},{%0,%1};"
        : "+r"(c[0]), "+r"(c[1])
        : "r"(a0), "r"(a1), "r"(a2), "r"(a3), "r"(b0), "r"(b1));
}
__device__ __forceinline__ void ldmx4(unsigned* r, unsigned addr) {
    asm volatile("ldmatrix.sync.aligned.m8n8.x4.shared.b16 {%0,%1,%2,%3},[%4];"
        : "=r"(r[0]), "=r"(r[1]), "=r"(r[2]), "=r"(r[3]) : "r"(addr));
}
__device__ __forceinline__ void ldmx4t(unsigned* r, unsigned addr) {
    asm volatile("ldmatrix.sync.aligned.m8n8.x4.trans.shared.b16 {%0,%1,%2,%3},[%4];"
        : "=r"(r[0]), "=r"(r[1]), "=r"(r[2]), "=r"(r[3]) : "r"(addr));
}
__device__ __forceinline__ void cpa16(void* dst, const void* src) {
    unsigned d = sptr(dst);
    asm volatile("cp.async.cg.shared.global [%0], [%1], 16;" :: "r"(d), "l"(src));
}
__device__ __forceinline__ void cp_commit() {
    asm volatile("cp.async.commit_group;");
}
template <int N>
__device__ __forceinline__ void cp_wait() {
    asm volatile("cp.async.wait_group %0;" :: "n"(N));
}
__device__ __forceinline__ unsigned h2(float a, float b) {
    __half2 h = __floats2half2_rn(a, b);
    return *reinterpret_cast<unsigned*>(&h);
}
__device__ __forceinline__ unsigned ex2h(unsigned x) {
    __half2 u = *reinterpret_cast<__half2*>(&x);
    const unsigned c15u = 0x4B804B80u;
    u = __hmin2(u, *reinterpret_cast<const __half2*>(&c15u));
    unsigned xx = *reinterpret_cast<unsigned*>(&u);
    unsigned y;
    asm("ex2.approx.f16x2 %0, %1;" : "=r"(y) : "r"(xx));
    return y;
}

// ---------------------------------------------------------------------------
// Batched pre-pass: round 5 fp32 arrays -> fp16 in ONE launch, MLP=4.
// ---------------------------------------------------------------------------
__global__ void round_all(
    const float4* s0, uint2* d0, int n0,
    const float4* s1, uint2* d1, int n1,
    const float4* s2, uint2* d2, int n2,
    const float4* s3, uint2* d3, int n3,
    const float4* s4, uint2* d4, int n4)
{
    const float4* s;
    uint2* d;
    int n;
    switch (blockIdx.y) {
        case 0: s = s0; d = d0; n = n0; break;
        case 1: s = s1; d = d1; n = n1; break;
        case 2: s = s2; d = d2; n = n2; break;
        case 3: s = s3; d = d3; n = n3; break;
        default: s = s4; d = d4; n = n4; break;
    }
    int base = blockIdx.x * (256 * 4) + threadIdx.x;
    float4 v[4];
    int idx[4];
    int cnt = 0;
#pragma unroll
    for (int u = 0; u < 4; u++) {
        int i = base + u * 256;
        if (i < n) { idx[cnt] = i; v[cnt] = s[i]; cnt++; }
    }
#pragma unroll
    for (int u = 0; u < 4; u++) {
        if (u < cnt) {
            uint2 o;
            o.x = h2(v[u].x, v[u].y);
            o.y = h2(v[u].z, v[u].w);
            d[idx[u]] = o;
        }
    }
}

// ---------------------------------------------------------------------------
// fp16 GEMM (R14/R15 best, reverted): block tile 64x64, 128 threads (4
// warps, warp tile 32x32), BK=64, 3-stage cp.async ring, 3 CTAs/SM.
// ---------------------------------------------------------------------------
#define PJ_STRIDE 72
#define PJX_BYTES (64 * PJ_STRIDE * 2)
#define PJW_BYTES (64 * PJ_STRIDE * 2)
#define PJ_STG    (PJX_BYTES + PJW_BYTES)
#define PJ_SMEM   (3 * PJ_STG)
#define PJ_NIT    (E_DIM / 64)

template <int LAYOUT>
__global__ __launch_bounds__(128, 3) void proj_mma(
    const __half* __restrict__ Xq, const __half* __restrict__ Xk,
    const __half* __restrict__ Xv,
    const __half* __restrict__ W, const float* __restrict__ bias,
    void* __restrict__ outq, void* __restrict__ outk, void* __restrict__ outv)
{
    extern __shared__ char psm[];

    const int tid  = threadIdx.x;
    const int lane = tid & 31;
    const int w    = tid >> 5;
    const int g    = lane >> 2;
    const int t    = lane & 3;
    const int quad = lane >> 3;
    const int lq   = lane & 7;
    const int wm   = w >> 1;
    const int wn   = w & 1;
    const int bm   = blockIdx.x * 64;
    const int bn   = blockIdx.y * 64;
    const int chunk = (LAYOUT == 0) ? (bn >> 10) : 0;

    const __half* X = (chunk == 0) ? Xq : (chunk == 1 ? Xk : Xv);

    float acc[2][4][4];
#pragma unroll
    for (int i = 0; i < 2; i++)
#pragma unroll
        for (int j = 0; j < 4; j++)
#pragma unroll
            for (int r = 0; r < 4; r++) acc[i][j][r] = 0.0f;

    const int cr = tid >> 3;
    const int cq = tid & 7;

    auto stage_load = [&](int st, int k0) {
        __half* Xs = reinterpret_cast<__half*>(psm + st * PJ_STG);
        __half* Ws = reinterpret_cast<__half*>(psm + st * PJ_STG + PJX_BYTES);
#pragma unroll
        for (int i = 0; i < 4; i++) {
            int r = cr + i * 16;
            cpa16(&Xs[r * PJ_STRIDE + cq * 8], X + (size_t)(bm + r) * E_DIM + k0 + cq * 8);
            cpa16(&Ws[r * PJ_STRIDE + cq * 8], W + (size_t)(bn + r) * E_DIM + k0 + cq * 8);
        }
        cp_commit();
    };

    stage_load(0, 0);
    stage_load(1, 64);

    const unsigned base0 = sptr(psm);
    const int a_row  = wm * 32 + (quad & 1) * 8 + lq;
    const int a_colB = ((quad >> 1) * 8) * 2;
    const int b_row  = wn * 32 + (quad >> 1) * 8 + lq;
    const int b_colB = ((quad & 1) * 8) * 2;

    for (int it = 0; it < PJ_NIT; ++it) {
        cp_wait<1>();
        __syncthreads();
        if (it + 2 < PJ_NIT) {
            stage_load((it + 2) % 3, (it + 2) * 64);
        } else {
            cp_commit();
        }

        const int st = it % 3;
        const unsigned xb = base0 + st * PJ_STG;
        const unsigned wb = xb + PJX_BYTES;
#pragma unroll
        for (int ks = 0; ks < 4; ++ks) {
            const int k0B = ks * 32;
            unsigned kb[2][4];
            unsigned a[2][4];
#pragma unroll
            for (int ng = 0; ng < 2; ++ng)
                ldmx4(kb[ng], wb + (unsigned)(b_row + ng * 16) * (PJ_STRIDE * 2) + k0B + b_colB);
#pragma unroll
            for (int mt = 0; mt < 2; ++mt)
                ldmx4(a[mt], xb + (unsigned)(a_row + mt * 16) * (PJ_STRIDE * 2) + k0B + a_colB);
#pragma unroll
            for (int mt = 0; mt < 2; ++mt)
#pragma unroll
                for (int ng = 0; ng < 2; ++ng) {
                    mma_f16(acc[mt][2 * ng],     a[mt][0], a[mt][1], a[mt][2], a[mt][3],
                            kb[ng][0], kb[ng][1]);
                    mma_f16(acc[mt][2 * ng + 1], a[mt][0], a[mt][1], a[mt][2], a[mt][3],
                            kb[ng][2], kb[ng][3]);
                }
        }
    }

    const float sc = (LAYOUT == 0 && chunk == 0) ? 0.1803368801111204f : 1.0f;
#pragma unroll
    for (int mt = 0; mt < 2; ++mt) {
        int r0 = bm + wm * 32 + mt * 16 + g;
#pragma unroll
        for (int nt = 0; nt < 4; ++nt) {
            int n = bn + wn * 32 + nt * 8 + 2 * t;
            float bv0 = bias[n];
            float bv1 = bias[n + 1];
            float v0 = acc[mt][nt][0] + bv0;
            float v1 = acc[mt][nt][1] + bv1;
            float v2 = acc[mt][nt][2] + bv0;
            float v3 = acc[mt][nt][3] + bv1;
            if (LAYOUT == 0) {
                int nn = n & 1023;
                int hh = nn >> 6;
                int dd = nn & 63;
                __half* dst = (__half*)((chunk == 0) ? outq : (chunk == 1 ? outk : outv));
                {
                    int r = r0;
                    size_t a0 = ((size_t)((r & 1) * H_DIM + hh) * T_DIM + (r >> 1)) * D_H + dd;
                    *reinterpret_cast<unsigned*>(&dst[a0]) = h2(v0 * sc, v1 * sc);
                }
                {
                    int r = r0 + 8;
                    size_t a1 = ((size_t)((r & 1) * H_DIM + hh) * T_DIM + (r >> 1)) * D_H + dd;
                    *reinterpret_cast<unsigned*>(&dst[a1]) = h2(v2 * sc, v3 * sc);
                }
            } else {
                float* dst = (float*)outq;
                *reinterpret_cast<float2*>(&dst[(size_t)r0 * E_DIM + n]) = make_float2(v0, v1);
                *reinterpret_cast<float2*>(&dst[(size_t)(r0 + 8) * E_DIM + n]) = make_float2(v2, v3);
            }
        }
    }
}

// ---------------------------------------------------------------------------
// fp16 flash attention, KV tile 128 (half the barriers of R14): 128-thread
// CTAs, Q tile 128 (32 rows/warp), 2-slot double buffer, 2 CTAs/SM.
// Per-thread register state identical to R14 (ng-loop runs 8 groups/iter).
// ---------------------------------------------------------------------------
#define QS_STRIDE 72
#define AQ_ROWS   128
#define KV_TILE   128
#define KV_HALVES (KV_TILE * QS_STRIDE)
#define ATTN_SMEM_HALVES (AQ_ROWS * QS_STRIDE + 2 * 2 * KV_HALVES)
#define ATTN_SMEM_BYTES  (ATTN_SMEM_HALVES * 2)   // 92160
#define N_KV (T_DIM / KV_TILE)                    // 16

__global__ __launch_bounds__(128, 2) void attn_mma(
    const __half* __restrict__ Q, const __half* __restrict__ K,
    const __half* __restrict__ V, __half* __restrict__ ctx)
{
    extern __shared__ __half smh[];
    __half* Qs  = smh;                        // [128][72]
    __half* KVs = smh + AQ_ROWS * QS_STRIDE;  // 2 slots {K[128][72], V[128][72]}

    const int tid  = threadIdx.x;
    const int lane = tid & 31;
    const int w    = tid >> 5;
    const int g    = lane >> 2;
    const int t    = lane & 3;
    const int quad = lane >> 3;
    const int lq   = lane & 7;
    const int qt   = blockIdx.x;
    const int bh   = blockIdx.y;
    const int b    = bh >> 4;
    const int h    = bh & 15;
    const int m0   = w * 32;

    const __half* Qh = Q + (size_t)bh * T_DIM * D_H + (size_t)qt * AQ_ROWS * D_H;
    const __half* Kh = K + (size_t)bh * T_DIM * D_H;
    const __half* Vh = V + (size_t)bh * T_DIM * D_H;

    const int lr = tid >> 3;                  // 0..15
    const int lc = tid & 7;

    auto kv_load = [&](int kv) {
        const int slot = kv & 1;
        __half* Kd = KVs + slot * 2 * KV_HALVES;
        __half* Vd = Kd + KV_HALVES;
        const __half* Kn = Kh + (size_t)kv * KV_TILE * D_H;
        const __half* Vn = Vh + (size_t)kv * KV_TILE * D_H;
#pragma unroll
        for (int i = 0; i < 8; i++) {
            int r = lr + i * 16;
            cpa16(&Kd[r * QS_STRIDE + lc * 8], Kn + (size_t)r * D_H + lc * 8);
            cpa16(&Vd[r * QS_STRIDE + lc * 8], Vn + (size_t)r * D_H + lc * 8);
        }
        cp_commit();
    };

    // prologue: Q, then KV slot 0
#pragma unroll
    for (int i = 0; i < 8; i++) {
        int r = lr + i * 16;
        cpa16(&Qs[r * QS_STRIDE + lc * 8], Qh + (size_t)r * D_H + lc * 8);
    }
    cp_commit();
    kv_load(0);

    cp_wait<1>();     // Q ready (kv0 still in flight)
    __syncthreads();

    const unsigned qbase  = sptr(Qs);
    const unsigned kvbase = sptr(KVs);
    unsigned qf[4][2][4];
    {
        int colB = ((quad >> 1) * 8) * 2;
#pragma unroll
        for (int mt = 0; mt < 2; ++mt) {
            int row = m0 + mt * 16 + (quad & 1) * 8 + lq;
#pragma unroll
            for (int kt = 0; kt < 4; ++kt)
                ldmx4(qf[kt][mt], qbase + (unsigned)row * (QS_STRIDE * 2) + kt * 32 + colB);
        }
    }

    float o[2][8][4];
#pragma unroll
    for (int mt = 0; mt < 2; mt++)
#pragma unroll
        for (int nt = 0; nt < 8; nt++)
#pragma unroll
            for (int r = 0; r < 4; r++) o[mt][nt][r] = 0.0f;
    float lacc[2][4];
#pragma unroll
    for (int mt = 0; mt < 2; mt++)
#pragma unroll
        for (int r = 0; r < 4; r++) lacc[mt][r] = 0.0f;
    const unsigned ONES = 0x3C003C00u;

    const int k_row  = (quad >> 1) * 8 + lq;
    const int k_colB = ((quad & 1) * 8) * 2;
    const int v_row  = (quad & 1) * 8 + lq;
    const int v_colB = ((quad >> 1) * 8) * 2;

    for (int kv = 0; kv < N_KV; ++kv) {
        cp_wait<0>();            // this iter's KV tile resident
        __syncthreads();         // all warps past previous slot use
        if (kv + 1 < N_KV)
            kv_load(kv + 1);     // overlaps with this iter's compute

        const unsigned kb_ = kvbase + (unsigned)(kv & 1) * (2 * KV_HALVES * 2);
        const unsigned vb_ = kb_ + KV_HALVES * 2;

        // 8 fused ng-groups per barrier: S(f16) -> ex2 -> l, PV
#pragma unroll
        for (int ng = 0; ng < 8; ++ng) {
            unsigned kb[4][4];
#pragma unroll
            for (int kt = 0; kt < 4; ++kt)
                ldmx4(kb[kt], kb_ + (unsigned)(ng * 16 + k_row) * (QS_STRIDE * 2) + kt * 32 + k_colB);

            unsigned pp[2][4];
#pragma unroll
            for (int mt = 0; mt < 2; ++mt) {
                unsigned s0[2] = {0u, 0u};
                unsigned s1[2] = {0u, 0u};
#pragma unroll
                for (int kt = 0; kt < 4; ++kt) {
                    mma_f16h(s0, qf[kt][mt][0], qf[kt][mt][1], qf[kt][mt][2], qf[kt][mt][3],
                             kb[kt][0], kb[kt][1]);
                    mma_f16h(s1, qf[kt][mt][0], qf[kt][mt][1], qf[kt][mt][2], qf[kt][mt][3],
                             kb[kt][2], kb[kt][3]);
                }
                pp[mt][0] = ex2h(s0[0]);
                pp[mt][1] = ex2h(s0[1]);
                pp[mt][2] = ex2h(s1[0]);
                pp[mt][3] = ex2h(s1[1]);
                mma_f16(lacc[mt], pp[mt][0], pp[mt][1], pp[mt][2], pp[mt][3], ONES, ONES);
            }

#pragma unroll
            for (int dg = 0; dg < 4; ++dg) {
                unsigned vb[4];
                ldmx4t(vb, vb_ + (unsigned)(ng * 16 + v_row) * (QS_STRIDE * 2) + dg * 32 + v_colB);
#pragma unroll
                for (int mt = 0; mt < 2; ++mt) {
                    mma_f16(o[mt][2 * dg],     pp[mt][0], pp[mt][1], pp[mt][2], pp[mt][3],
                            vb[0], vb[1]);
                    mma_f16(o[mt][2 * dg + 1], pp[mt][0], pp[mt][1], pp[mt][2], pp[mt][3],
                            vb[2], vb[3]);
                }
            }
        }
    }

#pragma unroll
    for (int mt = 0; mt < 2; ++mt) {
        float inv0 = 1.0f / lacc[mt][0];
        float inv1 = 1.0f / lacc[mt][2];
        int r0 = qt * AQ_ROWS + m0 + mt * 16 + g;
#pragma unroll
        for (int nt = 0; nt < 8; ++nt) {
            int d = nt * 8 + 2 * t;
            size_t a0 = ((size_t)r0 * B_DIM + b) * E_DIM + h * 64 + d;
            size_t a1 = ((size_t)(r0 + 8) * B_DIM + b) * E_DIM + h * 64 + d;
            *reinterpret_cast<unsigned*>(&ctx[a0]) = h2(o[mt][nt][0] * inv0, o[mt][nt][1] * inv0);
            *reinterpret_cast<unsigned*>(&ctx[a1]) = h2(o[mt][nt][2] * inv1, o[mt][nt][3] * inv1);
        }
    }
}

// ---------------------------------------------------------------------------
extern "C" void kernel_launch(void* const* d_in, const int* in_sizes, int n_in,
                              void* d_out, int out_size)
{
    const float* query = (const float*)d_in[0];
    const float* key   = (const float*)d_in[1];
    const float* value = (const float*)d_in[2];
    const float* in_w  = (const float*)d_in[3];
    const float* in_b  = (const float*)d_in[4];
    const float* out_w = (const float*)d_in[5];
    const float* out_b = (const float*)d_in[6];
    float* out = (float*)d_out;

    __half *qp, *kp, *vp, *cp, *xq, *xk, *xv, *wi, *wo;
    cudaGetSymbolAddress((void**)&qp, g_q);
    cudaGetSymbolAddress((void**)&kp, g_k);
    cudaGetSymbolAddress((void**)&vp, g_v);
    cudaGetSymbolAddress((void**)&cp, g_ctx);
    cudaGetSymbolAddress((void**)&xq, g_xq);
    cudaGetSymbolAddress((void**)&xk, g_xk);
    cudaGetSymbolAddress((void**)&xv, g_xv);
    cudaGetSymbolAddress((void**)&wi, g_wi);
    cudaGetSymbolAddress((void**)&wo, g_wo);

    cudaFuncSetAttribute(attn_mma, cudaFuncAttributeMaxDynamicSharedMemorySize,
                         ATTN_SMEM_BYTES);
    cudaFuncSetAttribute(proj_mma<0>, cudaFuncAttributeMaxDynamicSharedMemorySize,
                         PJ_SMEM);
    cudaFuncSetAttribute(proj_mma<1>, cudaFuncAttributeMaxDynamicSharedMemorySize,
                         PJ_SMEM);

    const int N_IN = M_DIM * E_DIM / 4;
    const int N_WI = 3 * E_DIM * E_DIM / 4;
    const int N_WO = E_DIM * E_DIM / 4;
    round_all<<<dim3((N_IN + 1023) / 1024, 5), 256>>>(
        (const float4*)query, (uint2*)xq, N_IN,
        (const float4*)key,   (uint2*)xk, N_IN,
        (const float4*)value, (uint2*)xv, N_IN,
        (const float4*)in_w,  (uint2*)wi, N_WI,
        (const float4*)out_w, (uint2*)wo, N_WO);

    proj_mma<0><<<dim3(M_DIM / 64, 48), 128, PJ_SMEM>>>(
        xq, xk, xv, wi, in_b, qp, kp, vp);

    attn_mma<<<dim3(T_DIM / AQ_ROWS, B_DIM * H_DIM), 128, ATTN_SMEM_BYTES>>>(qp, kp, vp, cp);

    proj_mma<1><<<dim3(M_DIM / 64, 16), 128, PJ_SMEM>>>(
        cp, cp, cp, wo, out_b, out, out, out);
}